// round 14
// baseline (speedup 1.0000x reference)
#include <cuda_runtime.h>
#include <cuda_bf16.h>
#include <stdint.h>
#include <math.h>

// ============================================================================
// MultiheadDiffAttention — mma.sync bf16x3 GEMMs + fused fp32 diff-attention
//   (tcgen05 unusable: harness ptxas target is compute_103, not _103a)
//   B=4, T=1024, E=1024, H=16 (v-heads), 2H=32 (q/k half-heads), D=32, 2D=64
// ============================================================================

#define BB 4
#define TT 1024
#define EE 1024
#define HH 16
#define MT (BB*TT)   // 4096 rows
#define KDIM 1024

static __device__ __constant__ float kLambdaInit   = 0.7836057665f;
static __device__ __constant__ float kOneMinusLI   = 0.2163942335f;
static __device__ __constant__ float kScaling      = 0.17677669529663687f; // 32^-0.5

// ---------------- scratch (static device arrays; no allocation) -------------
__device__ float g_Q[MT * EE];
__device__ float g_K[MT * EE];
__device__ float g_V[MT * EE];
__device__ float g_lambda;

__device__ __nv_bfloat16 g_xhi[MT * EE];
__device__ __nv_bfloat16 g_xlo[MT * EE];
__device__ __nv_bfloat16 g_wqh[EE * EE];
__device__ __nv_bfloat16 g_wql[EE * EE];
__device__ __nv_bfloat16 g_wkh[EE * EE];
__device__ __nv_bfloat16 g_wkl[EE * EE];
__device__ __nv_bfloat16 g_wvh[EE * EE];
__device__ __nv_bfloat16 g_wvl[EE * EE];
__device__ __nv_bfloat16 g_woh[EE * EE];
__device__ __nv_bfloat16 g_wol[EE * EE];
__device__ __nv_bfloat16 g_ahi[MT * EE];
__device__ __nv_bfloat16 g_alo[MT * EE];

// ============================================================================
// helpers
// ============================================================================
__device__ __forceinline__ uint32_t smem_u32(const void* p) {
    uint32_t a;
    asm("{ .reg .u64 t; cvta.to.shared.u64 t, %1; cvt.u32.u64 %0, t; }"
        : "=r"(a) : "l"(p));
    return a;
}
__device__ __forceinline__ void ldsm_x4(uint32_t& r0, uint32_t& r1,
                                        uint32_t& r2, uint32_t& r3, uint32_t addr) {
    asm volatile("ldmatrix.sync.aligned.m8n8.x4.shared.b16 {%0,%1,%2,%3}, [%4];"
                 : "=r"(r0), "=r"(r1), "=r"(r2), "=r"(r3) : "r"(addr));
}
__device__ __forceinline__ void ldsm_x2(uint32_t& r0, uint32_t& r1, uint32_t addr) {
    asm volatile("ldmatrix.sync.aligned.m8n8.x2.shared.b16 {%0,%1}, [%2];"
                 : "=r"(r0), "=r"(r1) : "r"(addr));
}
__device__ __forceinline__ void mma16816(float* c, const uint32_t* a, const uint32_t* b) {
    asm volatile(
        "mma.sync.aligned.m16n8k16.row.col.f32.bf16.bf16.f32 "
        "{%0,%1,%2,%3}, {%4,%5,%6,%7}, {%8,%9}, {%0,%1,%2,%3};"
        : "+f"(c[0]), "+f"(c[1]), "+f"(c[2]), "+f"(c[3])
        : "r"(a[0]), "r"(a[1]), "r"(a[2]), "r"(a[3]), "r"(b[0]), "r"(b[1]));
}

// ============================================================================
// lambda scalar
// ============================================================================
__global__ void lambda_kernel(const float* __restrict__ lq1, const float* __restrict__ lk1,
                              const float* __restrict__ lq2, const float* __restrict__ lk2) {
    int i = threadIdx.x;
    float a = lq1[i] * lk1[i];
    float b = lq2[i] * lk2[i];
    #pragma unroll
    for (int m = 16; m >= 1; m >>= 1) {
        a += __shfl_xor_sync(0xffffffffu, a, m);
        b += __shfl_xor_sync(0xffffffffu, b, m);
    }
    if (i == 0) g_lambda = expf(a) - expf(b) + kLambdaInit;
}

// ============================================================================
// fp32 -> (hi, lo) bf16 split.  x ≈ hi + lo, |err| <= 2^-17 |x|
// ============================================================================
__global__ void split_kernel(const float* __restrict__ in, __nv_bfloat16* __restrict__ hi,
                             __nv_bfloat16* __restrict__ lo, int n4) {
    int i = blockIdx.x * blockDim.x + threadIdx.x;
    if (i >= n4) return;
    float4 v = ((const float4*)in)[i];
    __nv_bfloat16 h0 = __float2bfloat16(v.x);
    __nv_bfloat16 h1 = __float2bfloat16(v.y);
    __nv_bfloat16 h2 = __float2bfloat16(v.z);
    __nv_bfloat16 h3 = __float2bfloat16(v.w);
    __nv_bfloat16 l0 = __float2bfloat16(v.x - __bfloat162float(h0));
    __nv_bfloat16 l1 = __float2bfloat16(v.y - __bfloat162float(h1));
    __nv_bfloat16 l2 = __float2bfloat16(v.z - __bfloat162float(h2));
    __nv_bfloat16 l3 = __float2bfloat16(v.w - __bfloat162float(h3));
    __nv_bfloat162 ph0, ph1, pl0, pl1;
    ph0.x = h0; ph0.y = h1; ph1.x = h2; ph1.y = h3;
    pl0.x = l0; pl0.y = l1; pl1.x = l2; pl1.y = l3;
    uint2 hv, lv;
    hv.x = *reinterpret_cast<uint32_t*>(&ph0);
    hv.y = *reinterpret_cast<uint32_t*>(&ph1);
    lv.x = *reinterpret_cast<uint32_t*>(&pl0);
    lv.y = *reinterpret_cast<uint32_t*>(&pl1);
    ((uint2*)hi)[i] = hv;
    ((uint2*)lo)[i] = lv;
}

// ============================================================================
// mma.sync bf16x3 GEMM:  C[m,n] = sum_k A[m,k]*B[n,k]  (fp32 result)
//   passes: (Ahi,Bhi), (Ahi,Blo), (Alo,Bhi); registers accumulate across all.
//   CTA: 128x128, BK=32 bf16, 256 threads, warp tile 64x32 (m16n8k16).
//   smem rows stride 80B -> conflict-free ldmatrix (banks 20r mod 32).
// ============================================================================
#define GSTRIDE_B 80                  // bytes per smem row (40 bf16)
#define GBUF_B_OFF 10240              // B tile after 128 A rows
#define GBUF_SZ   20480               // one stage (A+B)
#define GEMM_SMEM (2 * GBUF_SZ)       // 40 KB double-buffered

__global__ __launch_bounds__(256, 2)
void gemm_bf16x3(const __nv_bfloat16* __restrict__ Ahi, const __nv_bfloat16* __restrict__ Alo,
                 const __nv_bfloat16* __restrict__ Bhi, const __nv_bfloat16* __restrict__ Blo,
                 float* __restrict__ C) {
    extern __shared__ char smem[];
    const uint32_t sb  = smem_u32(smem);
    const int tid = threadIdx.x;
    const int lid = tid & 31;
    const int wid = tid >> 5;
    const int wm  = wid & 1;          // 2 warps along M (64 rows each)
    const int wn  = wid >> 1;         // 4 warps along N (32 cols each)
    const int rowB = blockIdx.y * 128;
    const int colB = blockIdx.x * 128;

    // global load coords: unit tid -> (row r0, 16B-chunk c0); unit tid+256 -> row r0+64
    const int r0 = tid >> 2;          // 0..63
    const int c0 = tid & 3;           // 0..3
    const uint32_t stoff = (uint32_t)(r0 * GSTRIDE_B + c0 * 16);

    // ldmatrix per-lane base offsets
    const uint32_t aOff = (uint32_t)((wm * 64 + (lid & 15)) * GSTRIDE_B + ((lid >> 4) & 1) * 16);
    const uint32_t bOff = (uint32_t)(GBUF_B_OFF + (wn * 32 + (lid & 7)) * GSTRIDE_B
                                     + ((lid >> 3) & 1) * 16);

    float acc[4][4][4];
    #pragma unroll
    for (int i = 0; i < 4; i++)
        #pragma unroll
        for (int j = 0; j < 4; j++)
            #pragma unroll
            for (int q = 0; q < 4; q++) acc[i][j][q] = 0.f;

    uint4 pfA0, pfA1, pfB0, pfB1;
    // prologue: load chunk 0 of pass 0 and stage into buffer 0
    {
        const __nv_bfloat16* Ap = Ahi;
        const __nv_bfloat16* Bp = Bhi;
        pfA0 = *(const uint4*)(Ap + (size_t)(rowB + r0) * KDIM + c0 * 8);
        pfA1 = *(const uint4*)(Ap + (size_t)(rowB + r0 + 64) * KDIM + c0 * 8);
        pfB0 = *(const uint4*)(Bp + (size_t)(colB + r0) * KDIM + c0 * 8);
        pfB1 = *(const uint4*)(Bp + (size_t)(colB + r0 + 64) * KDIM + c0 * 8);
        char* d = smem;
        *(uint4*)(d + stoff)                              = pfA0;
        *(uint4*)(d + stoff + 64 * GSTRIDE_B)             = pfA1;
        *(uint4*)(d + GBUF_B_OFF + stoff)                 = pfB0;
        *(uint4*)(d + GBUF_B_OFF + stoff + 64 * GSTRIDE_B) = pfB1;
    }
    __syncthreads();

    for (int it = 0; it < 96; it++) {
        const int nx = it + 1;
        if (nx < 96) {
            const int pass = nx >> 5;
            const int ch   = nx & 31;
            const __nv_bfloat16* Ap = (pass == 2) ? Alo : Ahi;
            const __nv_bfloat16* Bp = (pass == 1) ? Blo : Bhi;
            const __nv_bfloat16* ab = Ap + ch * 32 + c0 * 8;
            const __nv_bfloat16* bb = Bp + ch * 32 + c0 * 8;
            pfA0 = *(const uint4*)(ab + (size_t)(rowB + r0) * KDIM);
            pfA1 = *(const uint4*)(ab + (size_t)(rowB + r0 + 64) * KDIM);
            pfB0 = *(const uint4*)(bb + (size_t)(colB + r0) * KDIM);
            pfB1 = *(const uint4*)(bb + (size_t)(colB + r0 + 64) * KDIM);
        }

        // compute on buffer (it & 1)
        const uint32_t bufb = sb + (uint32_t)(it & 1) * GBUF_SZ;
        #pragma unroll
        for (int ks = 0; ks < 2; ks++) {
            uint32_t af[4][4], bf[4][2];
            #pragma unroll
            for (int i = 0; i < 4; i++)
                ldsm_x4(af[i][0], af[i][1], af[i][2], af[i][3],
                        bufb + aOff + (uint32_t)(i * 16 * GSTRIDE_B + ks * 32));
            #pragma unroll
            for (int j = 0; j < 4; j++)
                ldsm_x2(bf[j][0], bf[j][1],
                        bufb + bOff + (uint32_t)(j * 8 * GSTRIDE_B + ks * 32));
            #pragma unroll
            for (int i = 0; i < 4; i++)
                #pragma unroll
                for (int j = 0; j < 4; j++)
                    mma16816(acc[i][j], af[i], bf[j]);
        }

        // stage prefetched chunk into the other buffer
        if (nx < 96) {
            char* d = smem + (nx & 1) * GBUF_SZ;
            *(uint4*)(d + stoff)                               = pfA0;
            *(uint4*)(d + stoff + 64 * GSTRIDE_B)              = pfA1;
            *(uint4*)(d + GBUF_B_OFF + stoff)                  = pfB0;
            *(uint4*)(d + GBUF_B_OFF + stoff + 64 * GSTRIDE_B) = pfB1;
        }
        __syncthreads();
    }

    // epilogue: fragment layout -> C (row-major, N = EE)
    const int rbase = rowB + wm * 64 + (lid >> 2);
    const int cbase = colB + wn * 32 + 2 * (lid & 3);
    #pragma unroll
    for (int i = 0; i < 4; i++) {
        #pragma unroll
        for (int j = 0; j < 4; j++) {
            const int row = rbase + i * 16;
            const int col = cbase + j * 8;
            float2 lo2 = {acc[i][j][0], acc[i][j][1]};
            float2 hi2 = {acc[i][j][2], acc[i][j][3]};
            *(float2*)(C + (size_t)row * EE + col)       = lo2;
            *(float2*)(C + (size_t)(row + 8) * EE + col) = hi2;
        }
    }
}

// ============================================================================
// 16-lane group reductions
// ============================================================================
__device__ __forceinline__ float redmax16(float v) {
    v = fmaxf(v, __shfl_xor_sync(0xffffffffu, v, 1));
    v = fmaxf(v, __shfl_xor_sync(0xffffffffu, v, 2));
    v = fmaxf(v, __shfl_xor_sync(0xffffffffu, v, 4));
    v = fmaxf(v, __shfl_xor_sync(0xffffffffu, v, 8));
    return v;
}
__device__ __forceinline__ float redsum16(float v) {
    v += __shfl_xor_sync(0xffffffffu, v, 1);
    v += __shfl_xor_sync(0xffffffffu, v, 2);
    v += __shfl_xor_sync(0xffffffffu, v, 4);
    v += __shfl_xor_sync(0xffffffffu, v, 8);
    return v;
}

// ============================================================================
// Fused differential attention (fp32), epilogue emits bf16 hi/lo split
// ============================================================================
#define ATTN_SMEM_FLOATS (5 * 64 * 68 + 6 * 64)
#define ATTN_SMEM_BYTES  (ATTN_SMEM_FLOATS * 4)

__global__ __launch_bounds__(256, 2)
void diffattn_kernel(const float* __restrict__ gvec) {
    extern __shared__ float sm[];
    float* Qs  = sm;
    float* Ks  = Qs + 64 * 68;
    float* Vs  = Ks + 64 * 68;
    float* P1  = Vs + 64 * 68;
    float* P2  = P1 + 64 * 68;
    float* m1  = P2 + 64 * 68;
    float* l1  = m1 + 64;
    float* m2  = l1 + 64;
    float* l2  = m2 + 64;
    float* rs1 = l2 + 64;
    float* rs2 = rs1 + 64;

    const int tid = threadIdx.x;
    const int bh  = blockIdx.y;
    const int b   = bh >> 4;
    const int hd  = bh & 15;
    const int q0  = blockIdx.x * 64;

    const float* Qg = g_Q + (size_t)(b * TT + q0) * EE + hd * 64;
    const float* Kg = g_K + (size_t)(b * TT) * EE + hd * 64;
    const float* Vg = g_V + (size_t)(b * TT) * EE + hd * 64;

    #pragma unroll
    for (int it = 0; it < 4; it++) {
        int idx = tid + it * 256;
        int tok = idx >> 4;
        int c4  = (idx & 15) * 4;
        *(float4*)&Qs[tok * 68 + c4] = *(const float4*)(Qg + (size_t)tok * EE + c4);
    }
    if (tid < 64) { m1[tid] = -1e30f; l1[tid] = 0.f; m2[tid] = -1e30f; l2[tid] = 0.f; }

    const int tm = tid >> 4;
    const int tn = tid & 15;

    float o1[4][4], o2[4][4];
    #pragma unroll
    for (int i = 0; i < 4; i++)
        #pragma unroll
        for (int j = 0; j < 4; j++) { o1[i][j] = 0.f; o2[i][j] = 0.f; }

    for (int kt = 0; kt < 16; kt++) {
        __syncthreads();
        #pragma unroll
        for (int it = 0; it < 4; it++) {
            int idx = tid + it * 256;
            int tok = idx >> 4;
            int c4  = (idx & 15) * 4;
            *(float4*)&Ks[tok * 68 + c4] =
                *(const float4*)(Kg + (size_t)(kt * 64 + tok) * EE + c4);
            *(float4*)&Vs[tok * 68 + c4] =
                *(const float4*)(Vg + (size_t)(kt * 64 + tok) * EE + c4);
        }
        __syncthreads();

        float s1[4][4], s2[4][4];
        #pragma unroll
        for (int i = 0; i < 4; i++)
            #pragma unroll
            for (int j = 0; j < 4; j++) { s1[i][j] = 0.f; s2[i][j] = 0.f; }

        #pragma unroll
        for (int d = 0; d < 32; d += 4) {
            float4 qa[4], kb[4];
            #pragma unroll
            for (int i = 0; i < 4; i++) qa[i] = *(const float4*)&Qs[(tm * 4 + i) * 68 + d];
            #pragma unroll
            for (int j = 0; j < 4; j++) kb[j] = *(const float4*)&Ks[(tn * 4 + j) * 68 + d];
            #pragma unroll
            for (int i = 0; i < 4; i++)
                #pragma unroll
                for (int j = 0; j < 4; j++)
                    s1[i][j] += qa[i].x * kb[j].x + qa[i].y * kb[j].y
                              + qa[i].z * kb[j].z + qa[i].w * kb[j].w;
        }
        #pragma unroll
        for (int d = 32; d < 64; d += 4) {
            float4 qa[4], kb[4];
            #pragma unroll
            for (int i = 0; i < 4; i++) qa[i] = *(const float4*)&Qs[(tm * 4 + i) * 68 + d];
            #pragma unroll
            for (int j = 0; j < 4; j++) kb[j] = *(const float4*)&Ks[(tn * 4 + j) * 68 + d];
            #pragma unroll
            for (int i = 0; i < 4; i++)
                #pragma unroll
                for (int j = 0; j < 4; j++)
                    s2[i][j] += qa[i].x * kb[j].x + qa[i].y * kb[j].y
                              + qa[i].z * kb[j].z + qa[i].w * kb[j].w;
        }
        #pragma unroll
        for (int i = 0; i < 4; i++)
            #pragma unroll
            for (int j = 0; j < 4; j++) { s1[i][j] *= kScaling; s2[i][j] *= kScaling; }

        #pragma unroll
        for (int i = 0; i < 4; i++) {
            int r = tm * 4 + i;
            {
                float tmax = fmaxf(fmaxf(s1[i][0], s1[i][1]), fmaxf(s1[i][2], s1[i][3]));
                tmax = redmax16(tmax);
                float mold = m1[r];
                float mnew = fmaxf(mold, tmax);
                float ps = 0.f;
                #pragma unroll
                for (int j = 0; j < 4; j++) {
                    float p = __expf(s1[i][j] - mnew);
                    P1[r * 68 + tn * 4 + j] = p;
                    ps += p;
                }
                ps = redsum16(ps);
                float sc = __expf(mold - mnew);
                if (tn == 0) { m1[r] = mnew; l1[r] = l1[r] * sc + ps; rs1[r] = sc; }
            }
            {
                float tmax = fmaxf(fmaxf(s2[i][0], s2[i][1]), fmaxf(s2[i][2], s2[i][3]));
                tmax = redmax16(tmax);
                float mold = m2[r];
                float mnew = fmaxf(mold, tmax);
                float ps = 0.f;
                #pragma unroll
                for (int j = 0; j < 4; j++) {
                    float p = __expf(s2[i][j] - mnew);
                    P2[r * 68 + tn * 4 + j] = p;
                    ps += p;
                }
                ps = redsum16(ps);
                float sc = __expf(mold - mnew);
                if (tn == 0) { m2[r] = mnew; l2[r] = l2[r] * sc + ps; rs2[r] = sc; }
            }
        }
        __syncwarp();

        #pragma unroll
        for (int i = 0; i < 4; i++) {
            int r = tm * 4 + i;
            float sc1 = rs1[r], sc2 = rs2[r];
            #pragma unroll
            for (int j = 0; j < 4; j++) { o1[i][j] *= sc1; o2[i][j] *= sc2; }
        }

        // ---- P @ V, vectorized ----
        for (int kk0 = 0; kk0 < 64; kk0 += 4) {
            float4 vv[4];
            #pragma unroll
            for (int j = 0; j < 4; j++) vv[j] = *(const float4*)&Vs[(kk0 + j) * 68 + tn * 4];
            #pragma unroll
            for (int i = 0; i < 4; i++) {
                int r = tm * 4 + i;
                float4 p1 = *(const float4*)&P1[r * 68 + kk0];
                float4 p2 = *(const float4*)&P2[r * 68 + kk0];
                float p1a[4] = {p1.x, p1.y, p1.z, p1.w};
                float p2a[4] = {p2.x, p2.y, p2.z, p2.w};
                #pragma unroll
                for (int j = 0; j < 4; j++) {
                    o1[i][0] = fmaf(p1a[j], vv[j].x, o1[i][0]);
                    o1[i][1] = fmaf(p1a[j], vv[j].y, o1[i][1]);
                    o1[i][2] = fmaf(p1a[j], vv[j].z, o1[i][2]);
                    o1[i][3] = fmaf(p1a[j], vv[j].w, o1[i][3]);
                    o2[i][0] = fmaf(p2a[j], vv[j].x, o2[i][0]);
                    o2[i][1] = fmaf(p2a[j], vv[j].y, o2[i][1]);
                    o2[i][2] = fmaf(p2a[j], vv[j].z, o2[i][2]);
                    o2[i][3] = fmaf(p2a[j], vv[j].w, o2[i][3]);
                }
            }
        }
    }

    __syncthreads();

    // ---- epilogue: lambda-combine, RMSNorm, affine; emit bf16 hi/lo ----
    const float lam = g_lambda;
    float gw[4];
    #pragma unroll
    for (int j = 0; j < 4; j++) gw[j] = gvec[tn * 4 + j];

    #pragma unroll
    for (int i = 0; i < 4; i++) {
        int r = tm * 4 + i;
        float il1 = 1.0f / l1[r];
        float il2 = 1.0f / l2[r];
        float v[4];
        float ssq = 0.f;
        #pragma unroll
        for (int j = 0; j < 4; j++) {
            v[j] = o1[i][j] * il1 - lam * (o2[i][j] * il2);
            ssq += v[j] * v[j];
        }
        ssq = redsum16(ssq);
        float rstd = rsqrtf(ssq * (1.0f / 64.0f) + 1e-5f);
        float ov[4];
        #pragma unroll
        for (int j = 0; j < 4; j++) ov[j] = v[j] * rstd * gw[j] * kOneMinusLI;

        __nv_bfloat16 h4[4], l4[4];
        #pragma unroll
        for (int j = 0; j < 4; j++) {
            h4[j] = __float2bfloat16(ov[j]);
            l4[j] = __float2bfloat16(ov[j] - __bfloat162float(h4[j]));
        }
        __nv_bfloat162 ph0, ph1, pl0, pl1;
        ph0.x = h4[0]; ph0.y = h4[1]; ph1.x = h4[2]; ph1.y = h4[3];
        pl0.x = l4[0]; pl0.y = l4[1]; pl1.x = l4[2]; pl1.y = l4[3];
        uint2 hv, lv;
        hv.x = *reinterpret_cast<uint32_t*>(&ph0);
        hv.y = *reinterpret_cast<uint32_t*>(&ph1);
        lv.x = *reinterpret_cast<uint32_t*>(&pl0);
        lv.y = *reinterpret_cast<uint32_t*>(&pl1);
        size_t e = (size_t)(b * TT + q0 + r) * EE + hd * 64 + tn * 4;
        *(uint2*)(g_ahi + e) = hv;
        *(uint2*)(g_alo + e) = lv;
    }
}

// ============================================================================
// Launch
// Inputs: 0 x, 1 Wq, 2 Wk, 3 Wv, 4 Wo, 5 lq1, 6 lk1, 7 lq2, 8 lk2, 9 g
// ============================================================================
extern "C" void kernel_launch(void* const* d_in, const int* in_sizes, int n_in,
                              void* d_out, int out_size) {
    const float* x   = (const float*)d_in[0];
    const float* Wq  = (const float*)d_in[1];
    const float* Wk  = (const float*)d_in[2];
    const float* Wv  = (const float*)d_in[3];
    const float* Wo  = (const float*)d_in[4];
    const float* lq1 = (const float*)d_in[5];
    const float* lk1 = (const float*)d_in[6];
    const float* lq2 = (const float*)d_in[7];
    const float* lk2 = (const float*)d_in[8];
    const float* gv  = (const float*)d_in[9];
    float* out = (float*)d_out;

    float *Qp, *Kp, *Vp;
    __nv_bfloat16 *xh, *xl, *qh, *ql, *kh, *kl, *vh, *vl, *oh, *ol, *ah, *al;
    cudaGetSymbolAddress((void**)&Qp, g_Q);
    cudaGetSymbolAddress((void**)&Kp, g_K);
    cudaGetSymbolAddress((void**)&Vp, g_V);
    cudaGetSymbolAddress((void**)&xh, g_xhi);
    cudaGetSymbolAddress((void**)&xl, g_xlo);
    cudaGetSymbolAddress((void**)&qh, g_wqh);
    cudaGetSymbolAddress((void**)&ql, g_wql);
    cudaGetSymbolAddress((void**)&kh, g_wkh);
    cudaGetSymbolAddress((void**)&kl, g_wkl);
    cudaGetSymbolAddress((void**)&vh, g_wvh);
    cudaGetSymbolAddress((void**)&vl, g_wvl);
    cudaGetSymbolAddress((void**)&oh, g_woh);
    cudaGetSymbolAddress((void**)&ol, g_wol);
    cudaGetSymbolAddress((void**)&ah, g_ahi);
    cudaGetSymbolAddress((void**)&al, g_alo);

    cudaFuncSetAttribute(diffattn_kernel,
                         cudaFuncAttributeMaxDynamicSharedMemorySize, ATTN_SMEM_BYTES);

    lambda_kernel<<<1, 32>>>(lq1, lk1, lq2, lk2);

    // splits
    split_kernel<<<(MT * EE / 4 + 255) / 256, 256>>>(x,  xh, xl, MT * EE / 4);
    split_kernel<<<(EE * EE / 4 + 255) / 256, 256>>>(Wq, qh, ql, EE * EE / 4);
    split_kernel<<<(EE * EE / 4 + 255) / 256, 256>>>(Wk, kh, kl, EE * EE / 4);
    split_kernel<<<(EE * EE / 4 + 255) / 256, 256>>>(Wv, vh, vl, EE * EE / 4);
    split_kernel<<<(EE * EE / 4 + 255) / 256, 256>>>(Wo, oh, ol, EE * EE / 4);

    dim3 gg(EE / 128, MT / 128);   // (8, 32)
    gemm_bf16x3<<<gg, 256, GEMM_SMEM>>>(xh, xl, qh, ql, Qp);
    gemm_bf16x3<<<gg, 256, GEMM_SMEM>>>(xh, xl, kh, kl, Kp);
    gemm_bf16x3<<<gg, 256, GEMM_SMEM>>>(xh, xl, vh, vl, Vp);

    diffattn_kernel<<<dim3(TT / 64, BB * HH), 256, ATTN_SMEM_BYTES>>>(gv);

    gemm_bf16x3<<<gg, 256, GEMM_SMEM>>>(ah, al, oh, ol, out);
}

// round 15
// speedup vs baseline: 1.0018x; 1.0018x over previous
#include <cuda_runtime.h>
#include <cuda_bf16.h>
#include <stdint.h>
#include <math.h>

// ============================================================================
// MultiheadDiffAttention — mma.sync bf16x3 GEMMs + fused fp32 diff-attention
//   (tcgen05 unusable: harness ptxas target is compute_103, not _103a)
//   B=4, T=1024, E=1024, H=16 (v-heads), 2H=32 (q/k half-heads), D=32, 2D=64
// ============================================================================

#define BB 4
#define TT 1024
#define EE 1024
#define HH 16
#define MT (BB*TT)   // 4096 rows
#define KDIM 1024

static __device__ __constant__ float kLambdaInit   = 0.7836057665f;
static __device__ __constant__ float kOneMinusLI   = 0.2163942335f;
static __device__ __constant__ float kScaling      = 0.17677669529663687f; // 32^-0.5

// ---------------- scratch (static device arrays; no allocation) -------------
__device__ float g_Q[MT * EE];
__device__ float g_K[MT * EE];
__device__ float g_V[MT * EE];
__device__ float g_lambda;

__device__ __nv_bfloat16 g_xhi[MT * EE];
__device__ __nv_bfloat16 g_xlo[MT * EE];
__device__ __nv_bfloat16 g_wqh[EE * EE];
__device__ __nv_bfloat16 g_wql[EE * EE];
__device__ __nv_bfloat16 g_wkh[EE * EE];
__device__ __nv_bfloat16 g_wkl[EE * EE];
__device__ __nv_bfloat16 g_wvh[EE * EE];
__device__ __nv_bfloat16 g_wvl[EE * EE];
__device__ __nv_bfloat16 g_woh[EE * EE];
__device__ __nv_bfloat16 g_wol[EE * EE];
__device__ __nv_bfloat16 g_ahi[MT * EE];
__device__ __nv_bfloat16 g_alo[MT * EE];

// ============================================================================
// helpers
// ============================================================================
__device__ __forceinline__ uint32_t smem_u32(const void* p) {
    uint32_t a;
    asm("{ .reg .u64 t; cvta.to.shared.u64 t, %1; cvt.u32.u64 %0, t; }"
        : "=r"(a) : "l"(p));
    return a;
}
__device__ __forceinline__ void ldsm_x4(uint32_t& r0, uint32_t& r1,
                                        uint32_t& r2, uint32_t& r3, uint32_t addr) {
    asm volatile("ldmatrix.sync.aligned.m8n8.x4.shared.b16 {%0,%1,%2,%3}, [%4];"
                 : "=r"(r0), "=r"(r1), "=r"(r2), "=r"(r3) : "r"(addr));
}
__device__ __forceinline__ void ldsm_x2(uint32_t& r0, uint32_t& r1, uint32_t addr) {
    asm volatile("ldmatrix.sync.aligned.m8n8.x2.shared.b16 {%0,%1}, [%2];"
                 : "=r"(r0), "=r"(r1) : "r"(addr));
}
__device__ __forceinline__ void mma16816(float* c, const uint32_t* a, const uint32_t* b) {
    asm volatile(
        "mma.sync.aligned.m16n8k16.row.col.f32.bf16.bf16.f32 "
        "{%0,%1,%2,%3}, {%4,%5,%6,%7}, {%8,%9}, {%0,%1,%2,%3};"
        : "+f"(c[0]), "+f"(c[1]), "+f"(c[2]), "+f"(c[3])
        : "r"(a[0]), "r"(a[1]), "r"(a[2]), "r"(a[3]), "r"(b[0]), "r"(b[1]));
}

// ============================================================================
// lambda scalar
// ============================================================================
__global__ void lambda_kernel(const float* __restrict__ lq1, const float* __restrict__ lk1,
                              const float* __restrict__ lq2, const float* __restrict__ lk2) {
    int i = threadIdx.x;
    float a = lq1[i] * lk1[i];
    float b = lq2[i] * lk2[i];
    #pragma unroll
    for (int m = 16; m >= 1; m >>= 1) {
        a += __shfl_xor_sync(0xffffffffu, a, m);
        b += __shfl_xor_sync(0xffffffffu, b, m);
    }
    if (i == 0) g_lambda = expf(a) - expf(b) + kLambdaInit;
}

// ============================================================================
// fp32 -> (hi, lo) bf16 split.  x ≈ hi + lo, |err| <= 2^-17 |x|
// ============================================================================
__global__ void split_kernel(const float* __restrict__ in, __nv_bfloat16* __restrict__ hi,
                             __nv_bfloat16* __restrict__ lo, int n4) {
    int i = blockIdx.x * blockDim.x + threadIdx.x;
    if (i >= n4) return;
    float4 v = ((const float4*)in)[i];
    __nv_bfloat16 h0 = __float2bfloat16(v.x);
    __nv_bfloat16 h1 = __float2bfloat16(v.y);
    __nv_bfloat16 h2 = __float2bfloat16(v.z);
    __nv_bfloat16 h3 = __float2bfloat16(v.w);
    __nv_bfloat16 l0 = __float2bfloat16(v.x - __bfloat162float(h0));
    __nv_bfloat16 l1 = __float2bfloat16(v.y - __bfloat162float(h1));
    __nv_bfloat16 l2 = __float2bfloat16(v.z - __bfloat162float(h2));
    __nv_bfloat16 l3 = __float2bfloat16(v.w - __bfloat162float(h3));
    __nv_bfloat162 ph0, ph1, pl0, pl1;
    ph0.x = h0; ph0.y = h1; ph1.x = h2; ph1.y = h3;
    pl0.x = l0; pl0.y = l1; pl1.x = l2; pl1.y = l3;
    uint2 hv, lv;
    hv.x = *reinterpret_cast<uint32_t*>(&ph0);
    hv.y = *reinterpret_cast<uint32_t*>(&ph1);
    lv.x = *reinterpret_cast<uint32_t*>(&pl0);
    lv.y = *reinterpret_cast<uint32_t*>(&pl1);
    ((uint2*)hi)[i] = hv;
    ((uint2*)lo)[i] = lv;
}

// ============================================================================
// mma.sync bf16x3 GEMM:  C[m,n] = sum_k A[m,k]*B[n,k]  (fp32 result)
//   passes: (Ahi,Bhi), (Ahi,Blo), (Alo,Bhi); registers accumulate across all.
//   CTA: 128x128, BK=32 bf16, 256 threads, warp tile 64x32 (m16n8k16).
//   smem rows stride 80B -> conflict-free ldmatrix (banks 20r mod 32).
// ============================================================================
#define GSTRIDE_B 80                  // bytes per smem row (40 bf16)
#define GBUF_B_OFF 10240              // B tile after 128 A rows
#define GBUF_SZ   20480               // one stage (A+B)
#define GEMM_SMEM (2 * GBUF_SZ)       // 40 KB double-buffered

__global__ __launch_bounds__(256, 2)
void gemm_bf16x3(const __nv_bfloat16* __restrict__ Ahi, const __nv_bfloat16* __restrict__ Alo,
                 const __nv_bfloat16* __restrict__ Bhi, const __nv_bfloat16* __restrict__ Blo,
                 float* __restrict__ C) {
    extern __shared__ char smem[];
    const uint32_t sb  = smem_u32(smem);
    const int tid = threadIdx.x;
    const int lid = tid & 31;
    const int wid = tid >> 5;
    const int wm  = wid & 1;          // 2 warps along M (64 rows each)
    const int wn  = wid >> 1;         // 4 warps along N (32 cols each)
    const int rowB = blockIdx.y * 128;
    const int colB = blockIdx.x * 128;

    // global load coords: unit tid -> (row r0, 16B-chunk c0); unit tid+256 -> row r0+64
    const int r0 = tid >> 2;          // 0..63
    const int c0 = tid & 3;           // 0..3
    const uint32_t stoff = (uint32_t)(r0 * GSTRIDE_B + c0 * 16);

    // ldmatrix per-lane base offsets
    const uint32_t aOff = (uint32_t)((wm * 64 + (lid & 15)) * GSTRIDE_B + ((lid >> 4) & 1) * 16);
    const uint32_t bOff = (uint32_t)(GBUF_B_OFF + (wn * 32 + (lid & 7)) * GSTRIDE_B
                                     + ((lid >> 3) & 1) * 16);

    float acc[4][4][4];
    #pragma unroll
    for (int i = 0; i < 4; i++)
        #pragma unroll
        for (int j = 0; j < 4; j++)
            #pragma unroll
            for (int q = 0; q < 4; q++) acc[i][j][q] = 0.f;

    uint4 pfA0, pfA1, pfB0, pfB1;
    // prologue: load chunk 0 of pass 0 and stage into buffer 0
    {
        const __nv_bfloat16* Ap = Ahi;
        const __nv_bfloat16* Bp = Bhi;
        pfA0 = *(const uint4*)(Ap + (size_t)(rowB + r0) * KDIM + c0 * 8);
        pfA1 = *(const uint4*)(Ap + (size_t)(rowB + r0 + 64) * KDIM + c0 * 8);
        pfB0 = *(const uint4*)(Bp + (size_t)(colB + r0) * KDIM + c0 * 8);
        pfB1 = *(const uint4*)(Bp + (size_t)(colB + r0 + 64) * KDIM + c0 * 8);
        char* d = smem;
        *(uint4*)(d + stoff)                              = pfA0;
        *(uint4*)(d + stoff + 64 * GSTRIDE_B)             = pfA1;
        *(uint4*)(d + GBUF_B_OFF + stoff)                 = pfB0;
        *(uint4*)(d + GBUF_B_OFF + stoff + 64 * GSTRIDE_B) = pfB1;
    }
    __syncthreads();

    for (int it = 0; it < 96; it++) {
        const int nx = it + 1;
        if (nx < 96) {
            const int pass = nx >> 5;
            const int ch   = nx & 31;
            const __nv_bfloat16* Ap = (pass == 2) ? Alo : Ahi;
            const __nv_bfloat16* Bp = (pass == 1) ? Blo : Bhi;
            const __nv_bfloat16* ab = Ap + ch * 32 + c0 * 8;
            const __nv_bfloat16* bb = Bp + ch * 32 + c0 * 8;
            pfA0 = *(const uint4*)(ab + (size_t)(rowB + r0) * KDIM);
            pfA1 = *(const uint4*)(ab + (size_t)(rowB + r0 + 64) * KDIM);
            pfB0 = *(const uint4*)(bb + (size_t)(colB + r0) * KDIM);
            pfB1 = *(const uint4*)(bb + (size_t)(colB + r0 + 64) * KDIM);
        }

        // compute on buffer (it & 1)
        const uint32_t bufb = sb + (uint32_t)(it & 1) * GBUF_SZ;
        #pragma unroll
        for (int ks = 0; ks < 2; ks++) {
            uint32_t af[4][4], bf[4][2];
            #pragma unroll
            for (int i = 0; i < 4; i++)
                ldsm_x4(af[i][0], af[i][1], af[i][2], af[i][3],
                        bufb + aOff + (uint32_t)(i * 16 * GSTRIDE_B + ks * 32));
            #pragma unroll
            for (int j = 0; j < 4; j++)
                ldsm_x2(bf[j][0], bf[j][1],
                        bufb + bOff + (uint32_t)(j * 8 * GSTRIDE_B + ks * 32));
            #pragma unroll
            for (int i = 0; i < 4; i++)
                #pragma unroll
                for (int j = 0; j < 4; j++)
                    mma16816(acc[i][j], af[i], bf[j]);
        }

        // stage prefetched chunk into the other buffer
        if (nx < 96) {
            char* d = smem + (nx & 1) * GBUF_SZ;
            *(uint4*)(d + stoff)                               = pfA0;
            *(uint4*)(d + stoff + 64 * GSTRIDE_B)              = pfA1;
            *(uint4*)(d + GBUF_B_OFF + stoff)                  = pfB0;
            *(uint4*)(d + GBUF_B_OFF + stoff + 64 * GSTRIDE_B) = pfB1;
        }
        __syncthreads();
    }

    // epilogue: fragment layout -> C (row-major, N = EE)
    const int rbase = rowB + wm * 64 + (lid >> 2);
    const int cbase = colB + wn * 32 + 2 * (lid & 3);
    #pragma unroll
    for (int i = 0; i < 4; i++) {
        #pragma unroll
        for (int j = 0; j < 4; j++) {
            const int row = rbase + i * 16;
            const int col = cbase + j * 8;
            float2 lo2 = {acc[i][j][0], acc[i][j][1]};
            float2 hi2 = {acc[i][j][2], acc[i][j][3]};
            *(float2*)(C + (size_t)row * EE + col)       = lo2;
            *(float2*)(C + (size_t)(row + 8) * EE + col) = hi2;
        }
    }
}

// ============================================================================
// 16-lane group reductions
// ============================================================================
__device__ __forceinline__ float redmax16(float v) {
    v = fmaxf(v, __shfl_xor_sync(0xffffffffu, v, 1));
    v = fmaxf(v, __shfl_xor_sync(0xffffffffu, v, 2));
    v = fmaxf(v, __shfl_xor_sync(0xffffffffu, v, 4));
    v = fmaxf(v, __shfl_xor_sync(0xffffffffu, v, 8));
    return v;
}
__device__ __forceinline__ float redsum16(float v) {
    v += __shfl_xor_sync(0xffffffffu, v, 1);
    v += __shfl_xor_sync(0xffffffffu, v, 2);
    v += __shfl_xor_sync(0xffffffffu, v, 4);
    v += __shfl_xor_sync(0xffffffffu, v, 8);
    return v;
}

// ============================================================================
// Fused differential attention (fp32), epilogue emits bf16 hi/lo split
// ============================================================================
#define ATTN_SMEM_FLOATS (5 * 64 * 68 + 6 * 64)
#define ATTN_SMEM_BYTES  (ATTN_SMEM_FLOATS * 4)

__global__ __launch_bounds__(256, 2)
void diffattn_kernel(const float* __restrict__ gvec) {
    extern __shared__ float sm[];
    float* Qs  = sm;
    float* Ks  = Qs + 64 * 68;
    float* Vs  = Ks + 64 * 68;
    float* P1  = Vs + 64 * 68;
    float* P2  = P1 + 64 * 68;
    float* m1  = P2 + 64 * 68;
    float* l1  = m1 + 64;
    float* m2  = l1 + 64;
    float* l2  = m2 + 64;
    float* rs1 = l2 + 64;
    float* rs2 = rs1 + 64;

    const int tid = threadIdx.x;
    const int bh  = blockIdx.y;
    const int b   = bh >> 4;
    const int hd  = bh & 15;
    const int q0  = blockIdx.x * 64;

    const float* Qg = g_Q + (size_t)(b * TT + q0) * EE + hd * 64;
    const float* Kg = g_K + (size_t)(b * TT) * EE + hd * 64;
    const float* Vg = g_V + (size_t)(b * TT) * EE + hd * 64;

    #pragma unroll
    for (int it = 0; it < 4; it++) {
        int idx = tid + it * 256;
        int tok = idx >> 4;
        int c4  = (idx & 15) * 4;
        *(float4*)&Qs[tok * 68 + c4] = *(const float4*)(Qg + (size_t)tok * EE + c4);
    }
    if (tid < 64) { m1[tid] = -1e30f; l1[tid] = 0.f; m2[tid] = -1e30f; l2[tid] = 0.f; }

    const int tm = tid >> 4;
    const int tn = tid & 15;

    float o1[4][4], o2[4][4];
    #pragma unroll
    for (int i = 0; i < 4; i++)
        #pragma unroll
        for (int j = 0; j < 4; j++) { o1[i][j] = 0.f; o2[i][j] = 0.f; }

    for (int kt = 0; kt < 16; kt++) {
        __syncthreads();
        #pragma unroll
        for (int it = 0; it < 4; it++) {
            int idx = tid + it * 256;
            int tok = idx >> 4;
            int c4  = (idx & 15) * 4;
            *(float4*)&Ks[tok * 68 + c4] =
                *(const float4*)(Kg + (size_t)(kt * 64 + tok) * EE + c4);
            *(float4*)&Vs[tok * 68 + c4] =
                *(const float4*)(Vg + (size_t)(kt * 64 + tok) * EE + c4);
        }
        __syncthreads();

        float s1[4][4], s2[4][4];
        #pragma unroll
        for (int i = 0; i < 4; i++)
            #pragma unroll
            for (int j = 0; j < 4; j++) { s1[i][j] = 0.f; s2[i][j] = 0.f; }

        #pragma unroll
        for (int d = 0; d < 32; d += 4) {
            float4 qa[4], kb[4];
            #pragma unroll
            for (int i = 0; i < 4; i++) qa[i] = *(const float4*)&Qs[(tm * 4 + i) * 68 + d];
            #pragma unroll
            for (int j = 0; j < 4; j++) kb[j] = *(const float4*)&Ks[(tn * 4 + j) * 68 + d];
            #pragma unroll
            for (int i = 0; i < 4; i++)
                #pragma unroll
                for (int j = 0; j < 4; j++)
                    s1[i][j] += qa[i].x * kb[j].x + qa[i].y * kb[j].y
                              + qa[i].z * kb[j].z + qa[i].w * kb[j].w;
        }
        #pragma unroll
        for (int d = 32; d < 64; d += 4) {
            float4 qa[4], kb[4];
            #pragma unroll
            for (int i = 0; i < 4; i++) qa[i] = *(const float4*)&Qs[(tm * 4 + i) * 68 + d];
            #pragma unroll
            for (int j = 0; j < 4; j++) kb[j] = *(const float4*)&Ks[(tn * 4 + j) * 68 + d];
            #pragma unroll
            for (int i = 0; i < 4; i++)
                #pragma unroll
                for (int j = 0; j < 4; j++)
                    s2[i][j] += qa[i].x * kb[j].x + qa[i].y * kb[j].y
                              + qa[i].z * kb[j].z + qa[i].w * kb[j].w;
        }
        #pragma unroll
        for (int i = 0; i < 4; i++)
            #pragma unroll
            for (int j = 0; j < 4; j++) { s1[i][j] *= kScaling; s2[i][j] *= kScaling; }

        #pragma unroll
        for (int i = 0; i < 4; i++) {
            int r = tm * 4 + i;
            {
                float tmax = fmaxf(fmaxf(s1[i][0], s1[i][1]), fmaxf(s1[i][2], s1[i][3]));
                tmax = redmax16(tmax);
                float mold = m1[r];
                float mnew = fmaxf(mold, tmax);
                float ps = 0.f;
                #pragma unroll
                for (int j = 0; j < 4; j++) {
                    float p = __expf(s1[i][j] - mnew);
                    P1[r * 68 + tn * 4 + j] = p;
                    ps += p;
                }
                ps = redsum16(ps);
                float sc = __expf(mold - mnew);
                if (tn == 0) { m1[r] = mnew; l1[r] = l1[r] * sc + ps; rs1[r] = sc; }
            }
            {
                float tmax = fmaxf(fmaxf(s2[i][0], s2[i][1]), fmaxf(s2[i][2], s2[i][3]));
                tmax = redmax16(tmax);
                float mold = m2[r];
                float mnew = fmaxf(mold, tmax);
                float ps = 0.f;
                #pragma unroll
                for (int j = 0; j < 4; j++) {
                    float p = __expf(s2[i][j] - mnew);
                    P2[r * 68 + tn * 4 + j] = p;
                    ps += p;
                }
                ps = redsum16(ps);
                float sc = __expf(mold - mnew);
                if (tn == 0) { m2[r] = mnew; l2[r] = l2[r] * sc + ps; rs2[r] = sc; }
            }
        }
        __syncwarp();

        #pragma unroll
        for (int i = 0; i < 4; i++) {
            int r = tm * 4 + i;
            float sc1 = rs1[r], sc2 = rs2[r];
            #pragma unroll
            for (int j = 0; j < 4; j++) { o1[i][j] *= sc1; o2[i][j] *= sc2; }
        }

        // ---- P @ V, vectorized ----
        for (int kk0 = 0; kk0 < 64; kk0 += 4) {
            float4 vv[4];
            #pragma unroll
            for (int j = 0; j < 4; j++) vv[j] = *(const float4*)&Vs[(kk0 + j) * 68 + tn * 4];
            #pragma unroll
            for (int i = 0; i < 4; i++) {
                int r = tm * 4 + i;
                float4 p1 = *(const float4*)&P1[r * 68 + kk0];
                float4 p2 = *(const float4*)&P2[r * 68 + kk0];
                float p1a[4] = {p1.x, p1.y, p1.z, p1.w};
                float p2a[4] = {p2.x, p2.y, p2.z, p2.w};
                #pragma unroll
                for (int j = 0; j < 4; j++) {
                    o1[i][0] = fmaf(p1a[j], vv[j].x, o1[i][0]);
                    o1[i][1] = fmaf(p1a[j], vv[j].y, o1[i][1]);
                    o1[i][2] = fmaf(p1a[j], vv[j].z, o1[i][2]);
                    o1[i][3] = fmaf(p1a[j], vv[j].w, o1[i][3]);
                    o2[i][0] = fmaf(p2a[j], vv[j].x, o2[i][0]);
                    o2[i][1] = fmaf(p2a[j], vv[j].y, o2[i][1]);
                    o2[i][2] = fmaf(p2a[j], vv[j].z, o2[i][2]);
                    o2[i][3] = fmaf(p2a[j], vv[j].w, o2[i][3]);
                }
            }
        }
    }

    __syncthreads();

    // ---- epilogue: lambda-combine, RMSNorm, affine; emit bf16 hi/lo ----
    const float lam = g_lambda;
    float gw[4];
    #pragma unroll
    for (int j = 0; j < 4; j++) gw[j] = gvec[tn * 4 + j];

    #pragma unroll
    for (int i = 0; i < 4; i++) {
        int r = tm * 4 + i;
        float il1 = 1.0f / l1[r];
        float il2 = 1.0f / l2[r];
        float v[4];
        float ssq = 0.f;
        #pragma unroll
        for (int j = 0; j < 4; j++) {
            v[j] = o1[i][j] * il1 - lam * (o2[i][j] * il2);
            ssq += v[j] * v[j];
        }
        ssq = redsum16(ssq);
        float rstd = rsqrtf(ssq * (1.0f / 64.0f) + 1e-5f);
        float ov[4];
        #pragma unroll
        for (int j = 0; j < 4; j++) ov[j] = v[j] * rstd * gw[j] * kOneMinusLI;

        __nv_bfloat16 h4[4], l4[4];
        #pragma unroll
        for (int j = 0; j < 4; j++) {
            h4[j] = __float2bfloat16(ov[j]);
            l4[j] = __float2bfloat16(ov[j] - __bfloat162float(h4[j]));
        }
        __nv_bfloat162 ph0, ph1, pl0, pl1;
        ph0.x = h4[0]; ph0.y = h4[1]; ph1.x = h4[2]; ph1.y = h4[3];
        pl0.x = l4[0]; pl0.y = l4[1]; pl1.x = l4[2]; pl1.y = l4[3];
        uint2 hv, lv;
        hv.x = *reinterpret_cast<uint32_t*>(&ph0);
        hv.y = *reinterpret_cast<uint32_t*>(&ph1);
        lv.x = *reinterpret_cast<uint32_t*>(&pl0);
        lv.y = *reinterpret_cast<uint32_t*>(&pl1);
        size_t e = (size_t)(b * TT + q0 + r) * EE + hd * 64 + tn * 4;
        *(uint2*)(g_ahi + e) = hv;
        *(uint2*)(g_alo + e) = lv;
    }
}

// ============================================================================
// Launch
// Inputs: 0 x, 1 Wq, 2 Wk, 3 Wv, 4 Wo, 5 lq1, 6 lk1, 7 lq2, 8 lk2, 9 g
// ============================================================================
extern "C" void kernel_launch(void* const* d_in, const int* in_sizes, int n_in,
                              void* d_out, int out_size) {
    const float* x   = (const float*)d_in[0];
    const float* Wq  = (const float*)d_in[1];
    const float* Wk  = (const float*)d_in[2];
    const float* Wv  = (const float*)d_in[3];
    const float* Wo  = (const float*)d_in[4];
    const float* lq1 = (const float*)d_in[5];
    const float* lk1 = (const float*)d_in[6];
    const float* lq2 = (const float*)d_in[7];
    const float* lk2 = (const float*)d_in[8];
    const float* gv  = (const float*)d_in[9];
    float* out = (float*)d_out;

    float *Qp, *Kp, *Vp;
    __nv_bfloat16 *xh, *xl, *qh, *ql, *kh, *kl, *vh, *vl, *oh, *ol, *ah, *al;
    cudaGetSymbolAddress((void**)&Qp, g_Q);
    cudaGetSymbolAddress((void**)&Kp, g_K);
    cudaGetSymbolAddress((void**)&Vp, g_V);
    cudaGetSymbolAddress((void**)&xh, g_xhi);
    cudaGetSymbolAddress((void**)&xl, g_xlo);
    cudaGetSymbolAddress((void**)&qh, g_wqh);
    cudaGetSymbolAddress((void**)&ql, g_wql);
    cudaGetSymbolAddress((void**)&kh, g_wkh);
    cudaGetSymbolAddress((void**)&kl, g_wkl);
    cudaGetSymbolAddress((void**)&vh, g_wvh);
    cudaGetSymbolAddress((void**)&vl, g_wvl);
    cudaGetSymbolAddress((void**)&oh, g_woh);
    cudaGetSymbolAddress((void**)&ol, g_wol);
    cudaGetSymbolAddress((void**)&ah, g_ahi);
    cudaGetSymbolAddress((void**)&al, g_alo);

    cudaFuncSetAttribute(diffattn_kernel,
                         cudaFuncAttributeMaxDynamicSharedMemorySize, ATTN_SMEM_BYTES);

    lambda_kernel<<<1, 32>>>(lq1, lk1, lq2, lk2);

    // splits
    split_kernel<<<(MT * EE / 4 + 255) / 256, 256>>>(x,  xh, xl, MT * EE / 4);
    split_kernel<<<(EE * EE / 4 + 255) / 256, 256>>>(Wq, qh, ql, EE * EE / 4);
    split_kernel<<<(EE * EE / 4 + 255) / 256, 256>>>(Wk, kh, kl, EE * EE / 4);
    split_kernel<<<(EE * EE / 4 + 255) / 256, 256>>>(Wv, vh, vl, EE * EE / 4);
    split_kernel<<<(EE * EE / 4 + 255) / 256, 256>>>(Wo, oh, ol, EE * EE / 4);

    dim3 gg(EE / 128, MT / 128);   // (8, 32)
    gemm_bf16x3<<<gg, 256, GEMM_SMEM>>>(xh, xl, qh, ql, Qp);
    gemm_bf16x3<<<gg, 256, GEMM_SMEM>>>(xh, xl, kh, kl, Kp);
    gemm_bf16x3<<<gg, 256, GEMM_SMEM>>>(xh, xl, vh, vl, Vp);

    diffattn_kernel<<<dim3(TT / 64, BB * HH), 256, ATTN_SMEM_BYTES>>>(gv);

    gemm_bf16x3<<<gg, 256, GEMM_SMEM>>>(ah, al, oh, ol, out);
}